// round 13
// baseline (speedup 1.0000x reference)
#include <cuda_runtime.h>
#include <cuda_fp16.h>

#define NN 200000
#define NNZC 3200000
#define NG 256
#define CAP 64   // slots per row bucket; deg ~ Binomial(3.2M,1/200K) mean 16, P(>64) ~ 0

// ---- packed fp32x2 helpers (sm_103a FFMA2 path) ----
#define PACK2(dst, lo, hi) \
    asm("mov.b64 %0, {%1, %2};" : "=l"(dst) : "r"(__float_as_uint(lo)), "r"(__float_as_uint(hi)))
#define FFMA2(acc, a, b) \
    asm("fma.rn.f32x2 %0, %1, %2, %0;" : "+l"(acc) : "l"(a), "l"(b))
__device__ __forceinline__ float hsum2(unsigned long long v) {
    unsigned int u, w;
    asm("mov.b64 {%0, %1}, %2;" : "=r"(u), "=r"(w) : "l"(v));
    return __uint_as_float(u) + __uint_as_float(w);
}

// ---------------- device scratch (no allocations allowed) ----------------
__device__ __align__(16) int    g_cnt_up[NN];
__device__ __align__(16) int    g_cnt_dn[NN];
__device__ __align__(16) int2   g_eu[(size_t)NN * CAP];   // padded buckets (col, val bits)
__device__ __align__(16) int2   g_ed[(size_t)NN * CAP];
__device__ __align__(16) __half g_H16a[(size_t)NN * 32];  // layer-1 GEMM output
__device__ __align__(16) __half g_H16b[(size_t)NN * 32];  // layer-2 GEMM output
__device__ __align__(16) __half g_Xb16[(size_t)NN * 32];  // layer-2 agg output
__device__ __align__(16) float  g_T1a[NN];
__device__ __align__(16) float  g_T1b[NN];
__device__ __align__(16) float  g_T2a[NN];
__device__ __align__(16) float  g_T2b[NN];
__device__ __align__(16) float  g_T4a[NN];
__device__ __align__(16) float  g_T4b[NN];
__device__ __align__(16) float  g_psum[NG * 64];
__device__ __align__(16) float  g_pcnt[NG];

// ---------------- zero scratch ----------------
__global__ void zero_kernel() {
    int i = blockIdx.x * blockDim.x + threadIdx.x;
    if (i < NN) { g_cnt_up[i] = 0; g_cnt_dn[i] = 0; }
    if (i < NG * 64) g_psum[i] = 0.f;
    if (i < NG) g_pcnt[i] = 0.f;
}

// ---------------- single-pass padded adjacency build ----------------
__global__ void fillpad_kernel(const int* __restrict__ ru, const float* __restrict__ vu,
                               const int* __restrict__ rd, const float* __restrict__ vd) {
    int e2 = blockIdx.x * blockDim.x + threadIdx.x;
    if (e2 >= NNZC / 2) return;
    int2 r0 = ((const int2*)ru)[e2];
    int2 c0 = ((const int2*)(ru + NNZC))[e2];
    float2 v0 = ((const float2*)vu)[e2];
    int2 r1 = ((const int2*)rd)[e2];
    int2 c1 = ((const int2*)(rd + NNZC))[e2];
    float2 v1 = ((const float2*)vd)[e2];
    int pa = atomicAdd(&g_cnt_up[r0.x], 1);
    int pb = atomicAdd(&g_cnt_up[r0.y], 1);
    int pc = atomicAdd(&g_cnt_dn[r1.x], 1);
    int pd = atomicAdd(&g_cnt_dn[r1.y], 1);
    if (pa < CAP) g_eu[(size_t)r0.x * CAP + pa] = make_int2(c0.x, __float_as_int(v0.x));
    if (pb < CAP) g_eu[(size_t)r0.y * CAP + pb] = make_int2(c0.y, __float_as_int(v0.y));
    if (pc < CAP) g_ed[(size_t)r1.x * CAP + pc] = make_int2(c1.x, __float_as_int(v1.x));
    if (pd < CAP) g_ed[(size_t)r1.y * CAP + pd] = make_int2(c1.y, __float_as_int(v1.y));
}

// ---------------- layer-1 GEMM (f32x2) + fused T1 = exp(|h| @ a2) ----------------
// Two heads of width 16 concatenated (FO=32), W layout [2][128][16], a2 [2][16].
__global__ __launch_bounds__(256) void gemm1_kernel(const float* __restrict__ Xext,
                                                    const float* __restrict__ W,
                                                    const float* __restrict__ a2) {
    constexpr int FI = 128, FO = 32, NT = 32;
    constexpr int G = 8, TN = 4;
    __shared__ unsigned long long Wsd[(FI / 2) * FO];
    __shared__ __align__(16) float Xs[NT * FI];
    __shared__ float a2s[FO];

    int tid = threadIdx.x;
    for (int i = tid; i < (FI / 2) * FO; i += 256) {
        int k2 = i / FO, j = i % FO;
        float wlo, whi;
        if (j < 16) {
            wlo = W[(2 * k2) * 16 + j];
            whi = W[(2 * k2 + 1) * 16 + j];
        } else {
            wlo = W[FI * 16 + (2 * k2) * 16 + (j - 16)];
            whi = W[FI * 16 + (2 * k2 + 1) * 16 + (j - 16)];
        }
        unsigned long long dd; PACK2(dd, wlo, whi);
        Wsd[i] = dd;
    }
    if (tid < FO) a2s[tid] = a2[tid];
    int nb = blockIdx.x * NT;
    {
        const float4* src = (const float4*)(Xext + (size_t)nb * FI);
        float4* dst = (float4*)Xs;
        for (int i = tid; i < NT * FI / 4; i += 256) dst[i] = src[i];
    }
    __syncthreads();

    int j = tid % FO, grp = tid / FO, lane = tid & 31;
    unsigned long long acc[TN];
#pragma unroll
    for (int t = 0; t < TN; ++t) acc[t] = 0ull;
    const float4* Xs4 = (const float4*)Xs;
#pragma unroll 4
    for (int k4 = 0; k4 < FI / 4; ++k4) {
        unsigned long long w01 = Wsd[(2 * k4 + 0) * FO + j];
        unsigned long long w23 = Wsd[(2 * k4 + 1) * FO + j];
#pragma unroll
        for (int t = 0; t < TN; ++t) {
            float4 x = Xs4[(grp + G * t) * (FI / 4) + k4];
            unsigned long long x01, x23;
            PACK2(x01, x.x, x.y);
            PACK2(x23, x.z, x.w);
            FFMA2(acc[t], x01, w01);
            FFMA2(acc[t], x23, w23);
        }
    }
    float h[TN];
#pragma unroll
    for (int t = 0; t < TN; ++t) {
        h[t] = hsum2(acc[t]);
        int node = nb + grp + G * t;
        g_H16a[(size_t)node * 32 + j] = __float2half_rn(h[t]);
    }
    float a = a2s[j];
#pragma unroll
    for (int t = 0; t < TN; ++t) {
        float v = fabsf(h[t]) * a;
        v += __shfl_xor_sync(0xffffffffu, v, 8);
        v += __shfl_xor_sync(0xffffffffu, v, 4);
        v += __shfl_xor_sync(0xffffffffu, v, 2);
        v += __shfl_xor_sync(0xffffffffu, v, 1);
        int node = nb + grp + G * t;
        if (lane == 0)  g_T1a[node] = __expf(v);
        if (lane == 16) g_T1b[node] = __expf(v);
    }
}

// ---------------- row aggregation helper (16 features, 4 subgroups of 8 lanes) ----------------
__device__ __forceinline__ float2 agg_row16(const int2* __restrict__ E, const float* __restrict__ T,
                                            const __half2* __restrict__ H2, int hoff,
                                            int base, int deg, int sub, int f2) {
    float d = 0.f;
    float2 acc = make_float2(0.f, 0.f);
    int end = base + deg;
    for (int e = base + sub; e < end; e += 4) {
        int2 cv = E[e];
        float t = T[cv.x];
        float w = t * __int_as_float(cv.y);
        d += t;
        float2 hv = __half22float2(H2[(size_t)cv.x * 16 + hoff + f2]);
        acc.x += w * hv.x;
        acc.y += w * hv.y;
    }
    acc.x += __shfl_xor_sync(0xffffffffu, acc.x, 8);
    acc.y += __shfl_xor_sync(0xffffffffu, acc.y, 8);
    d     += __shfl_xor_sync(0xffffffffu, d, 8);
    acc.x += __shfl_xor_sync(0xffffffffu, acc.x, 16);
    acc.y += __shfl_xor_sync(0xffffffffu, acc.y, 16);
    d     += __shfl_xor_sync(0xffffffffu, d, 16);
    float rd = (d > 0.f) ? 1.f / d : 0.f;
    return make_float2(acc.x * rd, acc.y * rd);
}

// ---------------- fusedA: agg(layer1) -> smem -> GEMM W2 -> H16b + T2 ----------------
__global__ __launch_bounds__(256) void fusedA_kernel(const float* __restrict__ W,
                                                     const float* __restrict__ a2) {
    constexpr int FI = 32, FO = 32, NT = 64, G = 8, TN = 8;
    __shared__ unsigned long long Wsd[(FI / 2) * FO];   // 4KB
    __shared__ __align__(16) float Xs[NT * FI];         // 8KB
    __shared__ float a2s[FO];

    int tid = threadIdx.x;
    for (int i = tid; i < (FI / 2) * FO; i += 256) {
        int k2 = i / FO, j = i % FO;
        float wlo, whi;
        if (j < 16) {
            wlo = W[(2 * k2) * 16 + j];
            whi = W[(2 * k2 + 1) * 16 + j];
        } else {
            wlo = W[FI * 16 + (2 * k2) * 16 + (j - 16)];
            whi = W[FI * 16 + (2 * k2 + 1) * 16 + (j - 16)];
        }
        unsigned long long dd; PACK2(dd, wlo, whi);
        Wsd[i] = dd;
    }
    if (tid < FO) a2s[tid] = a2[tid];
    int nb = blockIdx.x * NT;

    // phase 1: each warp aggregates 8 rows (layer-1 features)
    {
        int wid = tid >> 5, lane = tid & 31, sub = lane >> 3, f2 = lane & 7;
        const __half2* H2 = (const __half2*)g_H16a;
        for (int k = 0; k < 8; ++k) {
            int row = nb + wid * 8 + k;
            int du = min(g_cnt_up[row], CAP);
            int dd = min(g_cnt_dn[row], CAP);
            float2 r0 = agg_row16(g_eu, g_T1a, H2, 0, row * CAP, du, sub, f2);
            float2 r1 = agg_row16(g_ed, g_T1b, H2, 8, row * CAP, dd, sub, f2);
            if (lane < 8) {
                float2* Xrow = (float2*)(Xs + (wid * 8 + k) * 32);
                Xrow[f2]     = make_float2(fmaxf(r0.x, 0.f), fmaxf(r0.y, 0.f));
                Xrow[8 + f2] = make_float2(fmaxf(r1.x, 0.f), fmaxf(r1.y, 0.f));
            }
        }
    }
    __syncthreads();

    // phase 2: GEMM layer 2
    int j = tid % FO, grp = tid / FO, lane = tid & 31;
    unsigned long long acc[TN];
#pragma unroll
    for (int t = 0; t < TN; ++t) acc[t] = 0ull;
    const float4* Xs4 = (const float4*)Xs;
#pragma unroll
    for (int k4 = 0; k4 < FI / 4; ++k4) {
        unsigned long long w01 = Wsd[(2 * k4 + 0) * FO + j];
        unsigned long long w23 = Wsd[(2 * k4 + 1) * FO + j];
#pragma unroll
        for (int t = 0; t < TN; ++t) {
            float4 x = Xs4[(grp + G * t) * (FI / 4) + k4];
            unsigned long long x01, x23;
            PACK2(x01, x.x, x.y);
            PACK2(x23, x.z, x.w);
            FFMA2(acc[t], x01, w01);
            FFMA2(acc[t], x23, w23);
        }
    }
    float h[TN];
#pragma unroll
    for (int t = 0; t < TN; ++t) {
        h[t] = hsum2(acc[t]);
        int node = nb + grp + G * t;
        g_H16b[(size_t)node * 32 + j] = __float2half_rn(h[t]);
    }
    float a = a2s[j];
#pragma unroll
    for (int t = 0; t < TN; ++t) {
        float v = fabsf(h[t]) * a;
        v += __shfl_xor_sync(0xffffffffu, v, 8);
        v += __shfl_xor_sync(0xffffffffu, v, 4);
        v += __shfl_xor_sync(0xffffffffu, v, 2);
        v += __shfl_xor_sync(0xffffffffu, v, 1);
        int node = nb + grp + G * t;
        if (lane == 0)  g_T2a[node] = __expf(v);
        if (lane == 16) g_T2b[node] = __expf(v);
    }
}

// ---------------- fusedB: agg(layer2) -> Xb16 + smem -> T4 (both heads) ----------------
__global__ __launch_bounds__(256) void fusedB_kernel(const float* __restrict__ W4,
                                                     const float* __restrict__ a24) {
    constexpr int FI = 32, FO = 64, NT = 64, G = 4, TN = 16;
    __shared__ unsigned long long Wsd[2 * (FI / 2) * FO];   // 16KB (both heads)
    __shared__ __align__(16) float Xs[NT * FI];             // 8KB
    __shared__ float a2s[2 * FO];
    __shared__ float sred[8 * TN];

    int tid = threadIdx.x;
    for (int i = tid; i < 2 * (FI / 2) * FO; i += 256) {
        int head = i / ((FI / 2) * FO);
        int ii = i - head * ((FI / 2) * FO);
        int k2 = ii / FO, j = ii % FO;
        const float* W = W4 + head * FI * FO;
        unsigned long long dd;
        PACK2(dd, W[(2 * k2) * FO + j], W[(2 * k2 + 1) * FO + j]);
        Wsd[i] = dd;
    }
    if (tid < 128) a2s[tid] = a24[tid];
    int nb = blockIdx.x * NT;

    // phase 1: aggregate layer-2 features; write Xb16 (needed by fusedC gather) + smem
    {
        int wid = tid >> 5, lane = tid & 31, sub = lane >> 3, f2 = lane & 7;
        const __half2* H2 = (const __half2*)g_H16b;
        __half2* XB = (__half2*)g_Xb16;
        for (int k = 0; k < 8; ++k) {
            int row = nb + wid * 8 + k;
            int du = min(g_cnt_up[row], CAP);
            int dd = min(g_cnt_dn[row], CAP);
            float2 r0 = agg_row16(g_eu, g_T2a, H2, 0, row * CAP, du, sub, f2);
            float2 r1 = agg_row16(g_ed, g_T2b, H2, 8, row * CAP, dd, sub, f2);
            if (lane < 8) {
                r0.x = fmaxf(r0.x, 0.f); r0.y = fmaxf(r0.y, 0.f);
                r1.x = fmaxf(r1.x, 0.f); r1.y = fmaxf(r1.y, 0.f);
                float2* Xrow = (float2*)(Xs + (wid * 8 + k) * 32);
                Xrow[f2] = r0;
                Xrow[8 + f2] = r1;
                XB[(size_t)row * 16 + f2]     = __float22half2_rn(r0);
                XB[(size_t)row * 16 + 8 + f2] = __float22half2_rn(r1);
            }
        }
    }
    __syncthreads();

    // phase 2: T4 for both heads
    int j = tid % FO, grp = tid / FO, lane = tid & 31, wib = tid >> 5;
    const float4* Xs4 = (const float4*)Xs;
    for (int head = 0; head < 2; ++head) {
        unsigned long long acc[TN];
#pragma unroll
        for (int t = 0; t < TN; ++t) acc[t] = 0ull;
        const unsigned long long* Wh = Wsd + head * (FI / 2) * FO;
#pragma unroll
        for (int k4 = 0; k4 < FI / 4; ++k4) {
            unsigned long long w01 = Wh[(2 * k4 + 0) * FO + j];
            unsigned long long w23 = Wh[(2 * k4 + 1) * FO + j];
#pragma unroll
            for (int t = 0; t < TN; ++t) {
                float4 x = Xs4[(grp + G * t) * (FI / 4) + k4];
                unsigned long long x01, x23;
                PACK2(x01, x.x, x.y);
                PACK2(x23, x.z, x.w);
                FFMA2(acc[t], x01, w01);
                FFMA2(acc[t], x23, w23);
            }
        }
        float a = a2s[head * 64 + j];
#pragma unroll
        for (int t = 0; t < TN; ++t) {
            float v = fabsf(hsum2(acc[t])) * a;
            for (int off = 16; off; off >>= 1) v += __shfl_xor_sync(0xffffffffu, v, off);
            if (lane == 0) sred[wib * TN + t] = v;
        }
        __syncthreads();
        if (j == 0) {
            float* Tout = head ? g_T4b : g_T4a;
#pragma unroll
            for (int t = 0; t < TN; ++t) {
                int node = nb + grp + G * t;
                Tout[node] = __expf(sred[(2 * grp) * TN + t] + sred[(2 * grp + 1) * TN + t]);
            }
        }
        __syncthreads();
    }
}

// ---------------- fusedC: agg4 -> smem -> final GEMM + ReLU + mean-pool ----------------
__global__ __launch_bounds__(256) void fusedC_kernel(const float* __restrict__ W4,
                                                     const int* __restrict__ batch) {
    constexpr int FI = 64, FO = 64, NT = 64, G = 4, TN = 16;
    __shared__ unsigned long long Wsd[(FI / 2) * FO];   // 16KB
    __shared__ __align__(16) float Us[NT * FI];         // 16KB
    __shared__ float sred2[4][64];

    int tid = threadIdx.x;
    for (int i = tid; i < (FI / 2) * FO; i += 256) {
        int k2 = i / FO, j = i % FO;
        unsigned long long dd;
        PACK2(dd, W4[(2 * k2) * FO + j], W4[(2 * k2 + 1) * FO + j]);
        Wsd[i] = dd;
    }
    int nb = blockIdx.x * NT;

    // phase 1: per warp, aggregate 8 rows of 32-dim Xb16 for up and dn graphs
    {
        int wid = tid >> 5, lane = tid & 31, sub = lane >> 4, f2 = lane & 15;
        const __half2* X2 = (const __half2*)g_Xb16;
        for (int k = 0; k < 8; ++k) {
            int row = nb + wid * 8 + k;
            float2 up, dn;
            {
                int base = row * CAP, deg = min(g_cnt_up[row], CAP);
                float d = 0.f;
                float2 acc = make_float2(0.f, 0.f);
                int end = base + deg;
                for (int e = base + sub; e < end; e += 2) {
                    int2 cv = g_eu[e];
                    float t = g_T4a[cv.x];
                    float w = t * __int_as_float(cv.y);
                    d += t;
                    float2 hv = __half22float2(X2[(size_t)cv.x * 16 + f2]);
                    acc.x += w * hv.x;
                    acc.y += w * hv.y;
                }
                acc.x += __shfl_xor_sync(0xffffffffu, acc.x, 16);
                acc.y += __shfl_xor_sync(0xffffffffu, acc.y, 16);
                d     += __shfl_xor_sync(0xffffffffu, d, 16);
                float rd = (d > 0.f) ? 1.f / d : 0.f;
                up = make_float2(acc.x * rd, acc.y * rd);
            }
            {
                int base = row * CAP, deg = min(g_cnt_dn[row], CAP);
                float d = 0.f;
                float2 acc = make_float2(0.f, 0.f);
                int end = base + deg;
                for (int e = base + sub; e < end; e += 2) {
                    int2 cv = g_ed[e];
                    float t = g_T4b[cv.x];
                    float w = t * __int_as_float(cv.y);
                    d += t;
                    float2 hv = __half22float2(X2[(size_t)cv.x * 16 + f2]);
                    acc.x += w * hv.x;
                    acc.y += w * hv.y;
                }
                acc.x += __shfl_xor_sync(0xffffffffu, acc.x, 16);
                acc.y += __shfl_xor_sync(0xffffffffu, acc.y, 16);
                d     += __shfl_xor_sync(0xffffffffu, d, 16);
                float rd = (d > 0.f) ? 1.f / d : 0.f;
                dn = make_float2(acc.x * rd, acc.y * rd);
            }
            if (lane < 16) {
                float2* Urow = (float2*)(Us + (wid * 8 + k) * 64);
                Urow[f2]      = up;    // up-agg -> cols [0,32)
                Urow[16 + f2] = dn;    // dn-agg -> cols [32,64)
            }
        }
    }
    __syncthreads();

    // phase 2: final GEMM (W4 flat [2][32][64] == [64][64]) + ReLU + pooled atomics
    int j = tid % FO, grp = tid / FO;
    unsigned long long acc[TN];
#pragma unroll
    for (int t = 0; t < TN; ++t) acc[t] = 0ull;
    const float4* Xs4 = (const float4*)Us;
#pragma unroll 4
    for (int k4 = 0; k4 < FI / 4; ++k4) {
        unsigned long long w01 = Wsd[(2 * k4 + 0) * FO + j];
        unsigned long long w23 = Wsd[(2 * k4 + 1) * FO + j];
#pragma unroll
        for (int t = 0; t < TN; ++t) {
            float4 x = Xs4[(grp + G * t) * (FI / 4) + k4];
            unsigned long long x01, x23;
            PACK2(x01, x.x, x.y);
            PACK2(x23, x.z, x.w);
            FFMA2(acc[t], x01, w01);
            FFMA2(acc[t], x23, w23);
        }
    }

    int b0 = batch[nb];
    int bL = batch[nb + NT - 1];
    if (b0 == bL) {
        float s = 0.f;
#pragma unroll
        for (int t = 0; t < TN; ++t) s += fmaxf(hsum2(acc[t]), 0.f);
        sred2[grp][j] = s;
        __syncthreads();
        if (tid < 64) {
            float tot = sred2[0][tid] + sred2[1][tid] + sred2[2][tid] + sred2[3][tid];
            atomicAdd(&g_psum[b0 * 64 + tid], tot);
        }
        if (tid == 0) atomicAdd(&g_pcnt[b0], (float)NT);
    } else {
#pragma unroll
        for (int t = 0; t < TN; ++t) {
            int node = nb + grp + G * t;
            int b = batch[node];
            atomicAdd(&g_psum[b * 64 + j], fmaxf(hsum2(acc[t]), 0.f));
            if (j == 0) atomicAdd(&g_pcnt[b], 1.f);
        }
    }
}

__global__ void pool_softmax_kernel(float* __restrict__ out) {
    int g = blockIdx.x, j = threadIdx.x;
    __shared__ float rm[2], rs[2];
    float c = g_pcnt[g];
    float mean = g_psum[g * 64 + j] / fmaxf(c, 1.0f);
    float m = mean;
    for (int off = 16; off; off >>= 1) m = fmaxf(m, __shfl_xor_sync(0xffffffffu, m, off));
    if ((j & 31) == 0) rm[j >> 5] = m;
    __syncthreads();
    m = fmaxf(rm[0], rm[1]);
    float e = expf(mean - m);
    float s = e;
    for (int off = 16; off; off >>= 1) s += __shfl_xor_sync(0xffffffffu, s, off);
    if ((j & 31) == 0) rs[j >> 5] = s;
    __syncthreads();
    s = rs[0] + rs[1];
    out[g * 64 + j] = e / s;
}

// ---------------- launch ----------------
extern "C" void kernel_launch(void* const* d_in, const int* in_sizes, int n_in,
                              void* d_out, int out_size) {
    const float* X1   = (const float*)d_in[0];
    const int*   idxu = (const int*)d_in[1];
    const float* valu = (const float*)d_in[2];
    const int*   idxd = (const int*)d_in[3];
    const float* vald = (const float*)d_in[4];
    const int*   batch = (const int*)d_in[5];
    const float* W1  = (const float*)d_in[6];
    const float* a21 = (const float*)d_in[8];
    const float* W2  = (const float*)d_in[9];
    const float* a22 = (const float*)d_in[11];
    const float* W4  = (const float*)d_in[12];
    const float* a24 = (const float*)d_in[14];
    float* out = (float*)d_out;

    const int NB = (NN + 255) / 256;     // 782

    zero_kernel<<<NB, 256>>>();
    fillpad_kernel<<<NNZC / 2 / 256, 256>>>(idxu, valu, idxd, vald);
    gemm1_kernel<<<NN / 32, 256>>>(X1, W1, a21);

    fusedA_kernel<<<NN / 64, 256>>>(W2, a22);     // agg L1 + GEMM W2 -> H16b, T2
    fusedB_kernel<<<NN / 64, 256>>>(W4, a24);     // agg L2 -> Xb16 + T4 (both heads)
    fusedC_kernel<<<NN / 64, 256>>>(W4, batch);   // agg4 + final GEMM + pool

    pool_softmax_kernel<<<NG, 64>>>(out);
}